// round 13
// baseline (speedup 1.0000x reference)
#include <cuda_runtime.h>
#include <cuda_bf16.h>
#include <math.h>

#define B_ 256
#define T_ 500
#define I_ 8
#define H_ 1024
#define O_ 8
#define ALPHA_ 0.2f
#define NSTD_ 0.05f

#define GRID_ 128
#define NTHR 512
#define PLANE 32768                 // one 128x128 bf16 plane (256B rows)

#define SM_B_OFF 0                  // 3 static M planes (96 KB, resident all steps)
#define SM_A_OFF 98304              // 3 r planes (96 KB, restaged per step; reused for D)
#define SMEM_BYTES 196608

// swizzled byte offset in a [row][256B] plane: XOR bits 5-7 with row&7
#define SWZ(row, cb) ((unsigned)((row) * 256 + ((cb) ^ (((row) & 7) << 5))))

__device__ float g_M[H_ * H_];                       // M[k][j] = relu(g[k])*effW[j][k]
__device__ __align__(16) unsigned short g_rs[3 * B_ * H_];  // r planes [p][b][h] bf16
__device__ float g_part[8 * H_ * B_];                // partials [ks][j][b]
__device__ float g_outp[B_ * O_ * 256];              // out partials [b][o][js]
__device__ unsigned g_bar;

__device__ __forceinline__ float softplus_f(float v) {
    return fmaxf(v, 0.0f) + log1pf(expf(-fabsf(v)));
}
__device__ __forceinline__ void cp16(unsigned dst, const void* src) {
    asm volatile("cp.async.cg.shared.global [%0], [%1], 16;" :: "r"(dst), "l"(src));
}
__device__ __forceinline__ void split3(float v, unsigned short* s) {
    __nv_bfloat16 b0 = __float2bfloat16_rn(v);
    float f1 = v - __bfloat162float(b0);
    __nv_bfloat16 b1 = __float2bfloat16_rn(f1);
    __nv_bfloat16 b2 = __float2bfloat16_rn(f1 - __bfloat162float(b1));
    s[0] = __bfloat16_as_ushort(b0);
    s[1] = __bfloat16_as_ushort(b1);
    s[2] = __bfloat16_as_ushort(b2);
}
__device__ __forceinline__ void mma16816(float* d, const unsigned* a, const unsigned* b) {
    asm volatile("mma.sync.aligned.m16n8k16.row.col.f32.bf16.bf16.f32 "
        "{%0,%1,%2,%3}, {%4,%5,%6,%7}, {%8,%9}, {%0,%1,%2,%3};"
        : "+f"(d[0]), "+f"(d[1]), "+f"(d[2]), "+f"(d[3])
        : "r"(a[0]), "r"(a[1]), "r"(a[2]), "r"(a[3]), "r"(b[0]), "r"(b[1]));
}

// ---- setup 0: build M + reset barrier ----
__global__ void k_build_M(const float* __restrict__ wrec, const float* __restrict__ mwrec,
                          const float* __restrict__ refEI, const float* __restrict__ g) {
    int n = blockIdx.x * blockDim.x + threadIdx.x;   // n = j*H + k
    if (n == 0) g_bar = 0u;
    if (n >= H_ * H_) return;
    int j = n >> 10, k = n & (H_ - 1);
    float ei = refEI[k];                              // exactly +/-1
    float e = fmaxf(wrec[n] * ei, 0.0f) * ei * mwrec[n];
    g_M[k * H_ + j] = fmaxf(g[k], 0.0f) * e;
}
// ---- setup 1: r(0) planes ----
__global__ void k_init_rs(const float* __restrict__ h0, const float* __restrict__ bvec) {
    int n = blockIdx.x * blockDim.x + threadIdx.x;
    if (n >= B_ * H_) return;
    int hh = n & (H_ - 1);
    unsigned short s[3];
    split3(softplus_f(h0[hh] + bvec[hh]), s);
#pragma unroll
    for (int p = 0; p < 3; ++p) g_rs[p * (B_ * H_) + n] = s[p];
}
// ---- setup 2: out0 + fill out[:,0,:] ----
__global__ void k_out0(const float* __restrict__ h0, const float* __restrict__ bvec,
                       const float* __restrict__ wout, float* __restrict__ out) {
    __shared__ float ws[8][O_]; __shared__ float o0[O_];
    int tid = threadIdx.x;
    float p[O_];
#pragma unroll
    for (int o = 0; o < O_; ++o) p[o] = 0.0f;
    for (int hh = tid; hh < H_; hh += 256) {
        float r0 = softplus_f(h0[hh] + bvec[hh]);
#pragma unroll
        for (int o = 0; o < O_; ++o) p[o] += r0 * wout[hh * O_ + o];
    }
#pragma unroll
    for (int d = 16; d > 0; d >>= 1)
#pragma unroll
        for (int o = 0; o < O_; ++o) p[o] += __shfl_xor_sync(0xffffffffu, p[o], d);
    if ((tid & 31) == 0) for (int o = 0; o < O_; ++o) ws[tid >> 5][o] = p[o];
    __syncthreads();
    if (tid < O_) { float s = 0; for (int w = 0; w < 8; ++w) s += ws[w][tid]; o0[tid] = s; }
    __syncthreads();
    for (int rep = 0; rep < 8; ++rep) {
        int P = rep * 256 + tid;
        out[(size_t)(P >> 3) * (T_ * O_) + (P & 7)] = o0[P & 7];
    }
}

// ---- persistent HMMA RNN ----
__global__ void __launch_bounds__(NTHR, 1)
k_rnn(const float* __restrict__ x, const float* __restrict__ noise,
      const float* __restrict__ wi, const float* __restrict__ wout,
      const float* __restrict__ bvec, const float* __restrict__ h0,
      float* __restrict__ out)
{
    extern __shared__ char smc[];
    unsigned su;
    asm("{ .reg .u64 t; cvta.to.shared.u64 t, %1; cvt.u32.u64 %0, t; }" : "=r"(su) : "l"(smc));

    const int tid = threadIdx.x, lane = tid & 31, w = tid >> 5, cta = blockIdx.x;
    const int bh = cta & 1, jt = (cta >> 1) & 7, ks = cta >> 4;
    const int j0 = jt * 128, k0 = ks * 128;
    const int m0 = (w & 3) * 32, n0 = (w >> 2) * 32;   // warp tile in CTA GEMM
    const int g = lane >> 2, tg = lane & 3;            // mma fragment coords
    // reducer role: b = tid&255, 4 j starting at cta*8 + (tid>>8)*4
    const int rb = tid & 255, rjj = tid >> 8, rjb = cta * 8 + rjj * 4;

    // ---- static B planes: Bp[j][k] = split_p(M[k0+k][j0+j]) ----
    for (int e = tid; e < 16384; e += NTHR) {
        int jl = e >> 7, k = e & 127;
        unsigned short s[3];
        split3(__ldg(g_M + (size_t)(k0 + k) * H_ + j0 + jl), s);
#pragma unroll
        for (int p = 0; p < 3; ++p)
            *(unsigned short*)(smc + SM_B_OFF + p * PLANE + SWZ(jl, k * 2)) = s[p];
    }
    float h[4], bT[4];
#pragma unroll
    for (int jj = 0; jj < 4; ++jj) { h[jj] = h0[rjb + jj]; bT[jj] = bvec[rjb + jj]; }
    __syncthreads();

    unsigned epoch = 0;
    for (int t = 0; t < T_ - 1; ++t) {
        // ---- stage A planes (r splits) via cp.async ----
#pragma unroll
        for (int rep = 0; rep < 12; ++rep) {
            int idx = rep * NTHR + tid;
            int p = idx >> 11, rem = idx & 2047, row = rem >> 4, ch = rem & 15;
            cp16(su + SM_A_OFF + p * PLANE + SWZ(row, ch * 16),
                 (const char*)g_rs + ((size_t)p * (B_ * H_)
                     + (size_t)(bh * 128 + row) * H_ + k0) * 2 + ch * 16);
        }
        asm volatile("cp.async.commit_group;" ::: "memory");

        // ---- overlapped: write out[:, t, :] from previous step's partials ----
        if (t >= 1 && tid < 16) {
            int P = cta * 16 + tid, b = P >> 3, o = P & 7;
            const float* src = g_outp + (size_t)b * 2048 + o * 256;
            float s = 0.0f;
#pragma unroll 8
            for (int js = 0; js < 256; ++js) s += __ldcv(src + js);
            out[(size_t)b * (T_ * O_) + (size_t)t * O_ + o] = s;
        }
        asm volatile("cp.async.wait_group 0;" ::: "memory");
        __syncthreads();

        // ---- GEMM: 6 split-products, fp32 accum ----
        float d[2][4][4];
#pragma unroll
        for (int mi = 0; mi < 2; ++mi)
#pragma unroll
            for (int ni = 0; ni < 4; ++ni)
#pragma unroll
                for (int q = 0; q < 4; ++q) d[mi][ni][q] = 0.0f;

#pragma unroll 1
        for (int kk = 0; kk < 8; ++kk) {
            const int cb0 = kk * 32 + tg * 4, cb1 = cb0 + 16;
            unsigned af[2][3][4], bf[4][3][2];
#pragma unroll
            for (int mi = 0; mi < 2; ++mi) {
                int r0 = m0 + mi * 16 + g, r1 = r0 + 8;
#pragma unroll
                for (int p = 0; p < 3; ++p) {
                    const char* base = smc + SM_A_OFF + p * PLANE;
                    af[mi][p][0] = *(const unsigned*)(base + SWZ(r0, cb0));
                    af[mi][p][1] = *(const unsigned*)(base + SWZ(r1, cb0));
                    af[mi][p][2] = *(const unsigned*)(base + SWZ(r0, cb1));
                    af[mi][p][3] = *(const unsigned*)(base + SWZ(r1, cb1));
                }
            }
#pragma unroll
            for (int ni = 0; ni < 4; ++ni) {
                int rw = n0 + ni * 8 + g;
#pragma unroll
                for (int p = 0; p < 3; ++p) {
                    const char* base = smc + SM_B_OFF + p * PLANE;
                    bf[ni][p][0] = *(const unsigned*)(base + SWZ(rw, cb0));
                    bf[ni][p][1] = *(const unsigned*)(base + SWZ(rw, cb1));
                }
            }
            const int PA[6] = {0, 0, 1, 1, 0, 2}, PB[6] = {0, 1, 0, 1, 2, 0};
#pragma unroll
            for (int pr = 0; pr < 6; ++pr)
#pragma unroll
                for (int mi = 0; mi < 2; ++mi)
#pragma unroll
                    for (int ni = 0; ni < 4; ++ni)
                        mma16816(d[mi][ni], af[mi][PA[pr]], bf[ni][PB[pr]]);
        }
        __syncthreads();                 // A reads done; reuse region for D staging

        // ---- D -> smem transposed [j][b] (stride 132 = conflict-free) ----
        float* sm_out = (float*)(smc + SM_A_OFF);
#pragma unroll
        for (int mi = 0; mi < 2; ++mi)
#pragma unroll
            for (int ni = 0; ni < 4; ++ni) {
                int jl = n0 + ni * 8 + tg * 2, bl = m0 + mi * 16 + g;
                sm_out[jl * 132 + bl]           = d[mi][ni][0];
                sm_out[(jl + 1) * 132 + bl]     = d[mi][ni][1];
                sm_out[jl * 132 + bl + 8]       = d[mi][ni][2];
                sm_out[(jl + 1) * 132 + bl + 8] = d[mi][ni][3];
            }
        __syncthreads();
#pragma unroll
        for (int rep = 0; rep < 8; ++rep) {
            int q = rep * NTHR + tid, jl = q >> 5, f4 = (q & 31) * 4;
            float4 v = *(const float4*)(sm_out + jl * 132 + f4);
            *(float4*)(g_part + (size_t)ks * (H_ * B_)
                       + (size_t)(j0 + jl) * B_ + bh * 128 + f4) = v;
        }
        // ---- barrier 1 ----
        epoch++; __syncthreads();
        if (tid == 0) {
            __threadfence(); atomicAdd(&g_bar, 1u);
            while (*(volatile unsigned*)&g_bar < epoch * GRID_) { }
        }
        __syncthreads();

        // ---- reducer: b = rb, j in [rjb, rjb+4) ----
        float acc[4] = {0.f, 0.f, 0.f, 0.f};
#pragma unroll
        for (int jj = 0; jj < 4; ++jj)
#pragma unroll
            for (int kr = 0; kr < 8; ++kr)
                acc[jj] += __ldcg(g_part + (size_t)kr * (H_ * B_)
                                  + (size_t)(rjb + jj) * B_ + rb);
        float4 xv0 = __ldg((const float4*)(x + (size_t)rb * (T_ * I_) + (size_t)t * I_));
        float4 xv1 = __ldg((const float4*)(x + (size_t)rb * (T_ * I_) + (size_t)t * I_ + 4));
        float4 nz = __ldg((const float4*)(noise + (size_t)rb * (T_ * H_) + (size_t)t * H_ + rjb));
        const float* nzp = &nz.x;
        float rn[4];
#pragma unroll
        for (int jj = 0; jj < 4; ++jj) {
            int j = rjb + jj;
            float inp = xv0.x * __ldg(wi + 0 * H_ + j) + xv0.y * __ldg(wi + 1 * H_ + j)
                      + xv0.z * __ldg(wi + 2 * H_ + j) + xv0.w * __ldg(wi + 3 * H_ + j)
                      + xv1.x * __ldg(wi + 4 * H_ + j) + xv1.y * __ldg(wi + 5 * H_ + j)
                      + xv1.z * __ldg(wi + 6 * H_ + j) + xv1.w * __ldg(wi + 7 * H_ + j);
            float hv = h[jj];
            hv = hv + NSTD_ * nzp[jj] + ALPHA_ * (-hv + acc[jj] + inp);
            h[jj] = hv;
            rn[jj] = softplus_f(hv + bT[jj]);
        }
        {
            unsigned short s0[3], s1[3], s2[3], s3[3];
            split3(rn[0], s0); split3(rn[1], s1); split3(rn[2], s2); split3(rn[3], s3);
#pragma unroll
            for (int p = 0; p < 3; ++p) {
                ushort4 v4 = make_ushort4(s0[p], s1[p], s2[p], s3[p]);
                *(ushort4*)(g_rs + (size_t)p * (B_ * H_) + (size_t)rb * H_ + rjb) = v4;
            }
        }
        float p[O_];
#pragma unroll
        for (int o = 0; o < O_; ++o) p[o] = 0.0f;
#pragma unroll
        for (int jj = 0; jj < 4; ++jj) {
            float4 w0 = __ldg((const float4*)(wout + (size_t)(rjb + jj) * O_));
            float4 w1 = __ldg((const float4*)(wout + (size_t)(rjb + jj) * O_ + 4));
            p[0] += rn[jj] * w0.x; p[1] += rn[jj] * w0.y;
            p[2] += rn[jj] * w0.z; p[3] += rn[jj] * w0.w;
            p[4] += rn[jj] * w1.x; p[5] += rn[jj] * w1.y;
            p[6] += rn[jj] * w1.z; p[7] += rn[jj] * w1.w;
        }
        int js = cta * 2 + rjj;
#pragma unroll
        for (int o = 0; o < O_; ++o)
            g_outp[(size_t)rb * 2048 + o * 256 + js] = p[o];
        // ---- barrier 2 ----
        epoch++; __syncthreads();
        if (tid == 0) {
            __threadfence(); atomicAdd(&g_bar, 1u);
            while (*(volatile unsigned*)&g_bar < epoch * GRID_) { }
        }
        __syncthreads();
    }

    // ---- final output: out[:, T-1, :] ----
    if (tid < 16) {
        int P = cta * 16 + tid, b = P >> 3, o = P & 7;
        const float* src = g_outp + (size_t)b * 2048 + o * 256;
        float s = 0.0f;
#pragma unroll 8
        for (int js = 0; js < 256; ++js) s += __ldcv(src + js);
        out[(size_t)b * (T_ * O_) + (size_t)(T_ - 1) * O_ + o] = s;
    }
}

extern "C" void kernel_launch(void* const* d_in, const int* in_sizes, int n_in,
                              void* d_out, int out_size) {
    const float* x     = (const float*)d_in[0];
    const float* noise = (const float*)d_in[1];
    const float* wi    = (const float*)d_in[2];
    const float* wrec  = (const float*)d_in[3];
    const float* wout  = (const float*)d_in[4];
    const float* bvec  = (const float*)d_in[5];
    const float* g     = (const float*)d_in[6];
    const float* h0    = (const float*)d_in[7];
    const float* refEI = (const float*)d_in[8];
    const float* mwrec = (const float*)d_in[9];
    float* out = (float*)d_out;

    cudaFuncSetAttribute(k_rnn, cudaFuncAttributeMaxDynamicSharedMemorySize, SMEM_BYTES);
    k_build_M<<<(H_ * H_ + 255) / 256, 256>>>(wrec, mwrec, refEI, g);
    k_init_rs<<<(B_ * H_ + 255) / 256, 256>>>(h0, bvec);
    k_out0<<<1, 256>>>(h0, bvec, wout, out);
    k_rnn<<<GRID_, NTHR, SMEM_BYTES>>>(x, noise, wi, wout, bvec, h0, out);
}

// round 14
// speedup vs baseline: 2.1077x; 2.1077x over previous
#include <cuda_runtime.h>
#include <cuda_bf16.h>
#include <math.h>

#define B_ 256
#define T_ 500
#define I_ 8
#define H_ 1024
#define O_ 8
#define ALPHA_ 0.2f
#define NSTD_ 0.05f

#define GRID_ 128
#define NTHR 512
#define PLANE 32768                 // one 128x128 bf16 plane (256B rows)

#define SM_B_OFF 0                  // 2 static M planes (64 KB, resident all steps)
#define SM_A_OFF 65536              // 2 r planes (64 KB, restaged per step; reused for D/s_po)
#define SMEM_BYTES 133120           // 65536 + 67584 (D staging 128*132*4)

// swizzled byte offset in a [row][256B] plane: XOR bits 5-7 with row&7
#define SWZ(row, cb) ((unsigned)((row) * 256 + ((cb) ^ (((row) & 7) << 5))))

__device__ float g_M[H_ * H_];                       // M[k][j] = relu(g[k])*effW[j][k]
__device__ __align__(16) unsigned short g_rs[2 * B_ * H_];  // r planes [p][b][h] bf16
__device__ float g_part[8 * H_ * B_];                // partials [ks][j][b]
__device__ float g_outp[128 * 2048];                 // out partials [cta][b*8+o]
__device__ unsigned g_bar;

__device__ __forceinline__ float softplus_f(float v) {
    return fmaxf(v, 0.0f) + log1pf(expf(-fabsf(v)));
}
__device__ __forceinline__ void cp16(unsigned dst, const void* src) {
    asm volatile("cp.async.cg.shared.global [%0], [%1], 16;" :: "r"(dst), "l"(src));
}
__device__ __forceinline__ void split2(float v, unsigned short* s) {
    __nv_bfloat16 b0 = __float2bfloat16_rn(v);
    __nv_bfloat16 b1 = __float2bfloat16_rn(v - __bfloat162float(b0));
    s[0] = __bfloat16_as_ushort(b0);
    s[1] = __bfloat16_as_ushort(b1);
}
__device__ __forceinline__ void mma16816(float* d, const unsigned* a, const unsigned* b) {
    asm volatile("mma.sync.aligned.m16n8k16.row.col.f32.bf16.bf16.f32 "
        "{%0,%1,%2,%3}, {%4,%5,%6,%7}, {%8,%9}, {%0,%1,%2,%3};"
        : "+f"(d[0]), "+f"(d[1]), "+f"(d[2]), "+f"(d[3])
        : "r"(a[0]), "r"(a[1]), "r"(a[2]), "r"(a[3]), "r"(b[0]), "r"(b[1]));
}

// ---- setup 0: build M + reset barrier ----
__global__ void k_build_M(const float* __restrict__ wrec, const float* __restrict__ mwrec,
                          const float* __restrict__ refEI, const float* __restrict__ g) {
    int n = blockIdx.x * blockDim.x + threadIdx.x;   // n = j*H + k
    if (n == 0) g_bar = 0u;
    if (n >= H_ * H_) return;
    int j = n >> 10, k = n & (H_ - 1);
    float ei = refEI[k];                              // exactly +/-1
    float e = fmaxf(wrec[n] * ei, 0.0f) * ei * mwrec[n];
    g_M[k * H_ + j] = fmaxf(g[k], 0.0f) * e;
}
// ---- setup 1: r(0) planes ----
__global__ void k_init_rs(const float* __restrict__ h0, const float* __restrict__ bvec) {
    int n = blockIdx.x * blockDim.x + threadIdx.x;
    if (n >= B_ * H_) return;
    int hh = n & (H_ - 1);
    unsigned short s[2];
    split2(softplus_f(h0[hh] + bvec[hh]), s);
#pragma unroll
    for (int p = 0; p < 2; ++p) g_rs[p * (B_ * H_) + n] = s[p];
}
// ---- setup 2: out0 + fill out[:,0,:] ----
__global__ void k_out0(const float* __restrict__ h0, const float* __restrict__ bvec,
                       const float* __restrict__ wout, float* __restrict__ out) {
    __shared__ float ws[8][O_]; __shared__ float o0[O_];
    int tid = threadIdx.x;
    float p[O_];
#pragma unroll
    for (int o = 0; o < O_; ++o) p[o] = 0.0f;
    for (int hh = tid; hh < H_; hh += 256) {
        float r0 = softplus_f(h0[hh] + bvec[hh]);
#pragma unroll
        for (int o = 0; o < O_; ++o) p[o] += r0 * wout[hh * O_ + o];
    }
#pragma unroll
    for (int d = 16; d > 0; d >>= 1)
#pragma unroll
        for (int o = 0; o < O_; ++o) p[o] += __shfl_xor_sync(0xffffffffu, p[o], d);
    if ((tid & 31) == 0) for (int o = 0; o < O_; ++o) ws[tid >> 5][o] = p[o];
    __syncthreads();
    if (tid < O_) { float s = 0; for (int w = 0; w < 8; ++w) s += ws[w][tid]; o0[tid] = s; }
    __syncthreads();
    for (int rep = 0; rep < 8; ++rep) {
        int P = rep * 256 + tid;
        out[(size_t)(P >> 3) * (T_ * O_) + (P & 7)] = o0[P & 7];
    }
}

// ---- persistent HMMA RNN ----
__global__ void __launch_bounds__(NTHR, 1)
k_rnn(const float* __restrict__ x, const float* __restrict__ noise,
      const float* __restrict__ wi, const float* __restrict__ wout,
      const float* __restrict__ bvec, const float* __restrict__ h0,
      float* __restrict__ out)
{
    extern __shared__ char smc[];
    unsigned su;
    asm("{ .reg .u64 t; cvta.to.shared.u64 t, %1; cvt.u32.u64 %0, t; }" : "=r"(su) : "l"(smc));

    const int tid = threadIdx.x, lane = tid & 31, w = tid >> 5, cta = blockIdx.x;
    const int bh = cta & 1, jt = (cta >> 1) & 7, ks = cta >> 4;
    const int j0 = jt * 128, k0 = ks * 128;
    const int m0 = (w & 3) * 32, n0 = (w >> 2) * 32;   // warp tile in CTA GEMM
    const int g = lane >> 2, tg = lane & 3;            // mma fragment coords
    // reducer role: b = tid&255, 4 j starting at cta*8 + (tid>>8)*4
    const int rb = tid & 255, rjj = tid >> 8, rjb = cta * 8 + rjj * 4;

    // ---- static B planes: Bp[j][k] = split_p(M[k0+k][j0+j]) ----
    for (int e = tid; e < 16384; e += NTHR) {
        int jl = e >> 7, k = e & 127;
        unsigned short s[2];
        split2(__ldg(g_M + (size_t)(k0 + k) * H_ + j0 + jl), s);
#pragma unroll
        for (int p = 0; p < 2; ++p)
            *(unsigned short*)(smc + SM_B_OFF + p * PLANE + SWZ(jl, k * 2)) = s[p];
    }
    float h[4], bT[4];
#pragma unroll
    for (int jj = 0; jj < 4; ++jj) { h[jj] = h0[rjb + jj]; bT[jj] = bvec[rjb + jj]; }
    __syncthreads();

    unsigned epoch = 0;
    for (int t = 0; t < T_ - 1; ++t) {
        // ---- stage A planes (r splits) via cp.async: 2 planes x 128 rows x 16 chunks ----
#pragma unroll
        for (int rep = 0; rep < 8; ++rep) {
            int idx = rep * NTHR + tid;
            int p = idx >> 11, rem = idx & 2047, row = rem >> 4, ch = rem & 15;
            cp16(su + SM_A_OFF + p * PLANE + SWZ(row, ch * 16),
                 (const char*)g_rs + ((size_t)p * (B_ * H_)
                     + (size_t)(bh * 128 + row) * H_ + k0) * 2 + ch * 16);
        }
        asm volatile("cp.async.commit_group;" ::: "memory");

        // ---- overlapped: out[:, t, :] from prev step's partials (parallel reduce) ----
        if (t >= 1 && tid < NTHR) {
            int pp = tid >> 5;                 // 16 (b,o) pairs per CTA
            int P = cta * 16 + pp;             // global b*8+o
            float v = __ldcg(g_outp + (size_t)lane * 2048 + P)
                    + __ldcg(g_outp + (size_t)(lane + 32) * 2048 + P)
                    + __ldcg(g_outp + (size_t)(lane + 64) * 2048 + P)
                    + __ldcg(g_outp + (size_t)(lane + 96) * 2048 + P);
#pragma unroll
            for (int d = 16; d > 0; d >>= 1) v += __shfl_xor_sync(0xffffffffu, v, d);
            if (lane == 0)
                out[(size_t)(P >> 3) * (T_ * O_) + (size_t)t * O_ + (P & 7)] = v;
        }
        asm volatile("cp.async.wait_group 0;" ::: "memory");
        __syncthreads();

        // ---- GEMM: 4 split-products (2-split x 2-split), fp32 accum ----
        float d[2][4][4];
#pragma unroll
        for (int mi = 0; mi < 2; ++mi)
#pragma unroll
            for (int ni = 0; ni < 4; ++ni)
#pragma unroll
                for (int q = 0; q < 4; ++q) d[mi][ni][q] = 0.0f;

#pragma unroll 1
        for (int kk = 0; kk < 8; ++kk) {
            const int cb0 = kk * 32 + tg * 4, cb1 = cb0 + 16;
            unsigned af[2][2][4], bf[4][2][2];
#pragma unroll
            for (int mi = 0; mi < 2; ++mi) {
                int r0 = m0 + mi * 16 + g, r1 = r0 + 8;
#pragma unroll
                for (int p = 0; p < 2; ++p) {
                    const char* base = smc + SM_A_OFF + p * PLANE;
                    af[mi][p][0] = *(const unsigned*)(base + SWZ(r0, cb0));
                    af[mi][p][1] = *(const unsigned*)(base + SWZ(r1, cb0));
                    af[mi][p][2] = *(const unsigned*)(base + SWZ(r0, cb1));
                    af[mi][p][3] = *(const unsigned*)(base + SWZ(r1, cb1));
                }
            }
#pragma unroll
            for (int ni = 0; ni < 4; ++ni) {
                int rw = n0 + ni * 8 + g;
#pragma unroll
                for (int p = 0; p < 2; ++p) {
                    const char* base = smc + SM_B_OFF + p * PLANE;
                    bf[ni][p][0] = *(const unsigned*)(base + SWZ(rw, cb0));
                    bf[ni][p][1] = *(const unsigned*)(base + SWZ(rw, cb1));
                }
            }
            const int PA[4] = {0, 0, 1, 1}, PB[4] = {0, 1, 0, 1};
#pragma unroll
            for (int pr = 0; pr < 4; ++pr)
#pragma unroll
                for (int mi = 0; mi < 2; ++mi)
#pragma unroll
                    for (int ni = 0; ni < 4; ++ni)
                        mma16816(d[mi][ni], af[mi][PA[pr]], bf[ni][PB[pr]]);
        }
        __syncthreads();                 // A reads done; reuse region for D staging

        // ---- D -> smem transposed [j][b] (stride 132 = conflict-free) ----
        float* sm_out = (float*)(smc + SM_A_OFF);
#pragma unroll
        for (int mi = 0; mi < 2; ++mi)
#pragma unroll
            for (int ni = 0; ni < 4; ++ni) {
                int jl = n0 + ni * 8 + tg * 2, bl = m0 + mi * 16 + g;
                sm_out[jl * 132 + bl]           = d[mi][ni][0];
                sm_out[(jl + 1) * 132 + bl]     = d[mi][ni][1];
                sm_out[jl * 132 + bl + 8]       = d[mi][ni][2];
                sm_out[(jl + 1) * 132 + bl + 8] = d[mi][ni][3];
            }
        __syncthreads();
#pragma unroll
        for (int rep = 0; rep < 8; ++rep) {
            int q = rep * NTHR + tid, jl = q >> 5, f4 = (q & 31) * 4;
            float4 v = *(const float4*)(sm_out + jl * 132 + f4);
            *(float4*)(g_part + (size_t)ks * (H_ * B_)
                       + (size_t)(j0 + jl) * B_ + bh * 128 + f4) = v;
        }
        // ---- barrier 1 ----
        epoch++; __syncthreads();
        if (tid == 0) {
            __threadfence(); atomicAdd(&g_bar, 1u);
            while (*(volatile unsigned*)&g_bar < epoch * GRID_) { }
        }
        __syncthreads();

        // ---- reducer: b = rb, j in [rjb, rjb+4) ----
        float acc[4] = {0.f, 0.f, 0.f, 0.f};
#pragma unroll
        for (int jj = 0; jj < 4; ++jj)
#pragma unroll
            for (int kr = 0; kr < 8; ++kr)
                acc[jj] += __ldcg(g_part + (size_t)kr * (H_ * B_)
                                  + (size_t)(rjb + jj) * B_ + rb);
        float4 xv0 = __ldg((const float4*)(x + (size_t)rb * (T_ * I_) + (size_t)t * I_));
        float4 xv1 = __ldg((const float4*)(x + (size_t)rb * (T_ * I_) + (size_t)t * I_ + 4));
        float4 nz = __ldg((const float4*)(noise + (size_t)rb * (T_ * H_) + (size_t)t * H_ + rjb));
        const float* nzp = &nz.x;
        float rn[4];
#pragma unroll
        for (int jj = 0; jj < 4; ++jj) {
            int j = rjb + jj;
            float inp = xv0.x * __ldg(wi + 0 * H_ + j) + xv0.y * __ldg(wi + 1 * H_ + j)
                      + xv0.z * __ldg(wi + 2 * H_ + j) + xv0.w * __ldg(wi + 3 * H_ + j)
                      + xv1.x * __ldg(wi + 4 * H_ + j) + xv1.y * __ldg(wi + 5 * H_ + j)
                      + xv1.z * __ldg(wi + 6 * H_ + j) + xv1.w * __ldg(wi + 7 * H_ + j);
            float hv = h[jj];
            hv = hv + NSTD_ * nzp[jj] + ALPHA_ * (-hv + acc[jj] + inp);
            h[jj] = hv;
            rn[jj] = softplus_f(hv + bT[jj]);
        }
        {
            unsigned short s0[2], s1[2], s2[2], s3[2];
            split2(rn[0], s0); split2(rn[1], s1); split2(rn[2], s2); split2(rn[3], s3);
#pragma unroll
            for (int p = 0; p < 2; ++p) {
                ushort4 v4 = make_ushort4(s0[p], s1[p], s2[p], s3[p]);
                *(ushort4*)(g_rs + (size_t)p * (B_ * H_) + (size_t)rb * H_ + rjb) = v4;
            }
        }
        float p[O_];
#pragma unroll
        for (int o = 0; o < O_; ++o) p[o] = 0.0f;
#pragma unroll
        for (int jj = 0; jj < 4; ++jj) {
            float4 w0 = __ldg((const float4*)(wout + (size_t)(rjb + jj) * O_));
            float4 w1 = __ldg((const float4*)(wout + (size_t)(rjb + jj) * O_ + 4));
            p[0] += rn[jj] * w0.x; p[1] += rn[jj] * w0.y;
            p[2] += rn[jj] * w0.z; p[3] += rn[jj] * w0.w;
            p[4] += rn[jj] * w1.x; p[5] += rn[jj] * w1.y;
            p[6] += rn[jj] * w1.z; p[7] += rn[jj] * w1.w;
        }
        // fold the two j-halves in smem, then ONE coalesced slice per CTA
        float* s_po = (float*)(smc + SM_A_OFF);     // 2 x 256 x 8 floats = 16 KB
        {
            float4* st = (float4*)(s_po + ((size_t)rjj * 256 + rb) * O_);
            st[0] = make_float4(p[0], p[1], p[2], p[3]);
            st[1] = make_float4(p[4], p[5], p[6], p[7]);
        }
        __syncthreads();
#pragma unroll
        for (int q = 0; q < 4; ++q) {
            int idx = tid * 4 + q;                  // b*8+o in [0,2048)
            g_outp[(size_t)cta * 2048 + idx] = s_po[idx] + s_po[2048 + idx];
        }
        // ---- barrier 2 ----
        epoch++; __syncthreads();
        if (tid == 0) {
            __threadfence(); atomicAdd(&g_bar, 1u);
            while (*(volatile unsigned*)&g_bar < epoch * GRID_) { }
        }
        __syncthreads();
    }

    // ---- final output: out[:, T-1, :] ----
    {
        int pp = tid >> 5, P = cta * 16 + pp;
        float v = __ldcg(g_outp + (size_t)lane * 2048 + P)
                + __ldcg(g_outp + (size_t)(lane + 32) * 2048 + P)
                + __ldcg(g_outp + (size_t)(lane + 64) * 2048 + P)
                + __ldcg(g_outp + (size_t)(lane + 96) * 2048 + P);
#pragma unroll
        for (int d = 16; d > 0; d >>= 1) v += __shfl_xor_sync(0xffffffffu, v, d);
        if (lane == 0)
            out[(size_t)(P >> 3) * (T_ * O_) + (size_t)(T_ - 1) * O_ + (P & 7)] = v;
    }
}

extern "C" void kernel_launch(void* const* d_in, const int* in_sizes, int n_in,
                              void* d_out, int out_size) {
    const float* x     = (const float*)d_in[0];
    const float* noise = (const float*)d_in[1];
    const float* wi    = (const float*)d_in[2];
    const float* wrec  = (const float*)d_in[3];
    const float* wout  = (const float*)d_in[4];
    const float* bvec  = (const float*)d_in[5];
    const float* g     = (const float*)d_in[6];
    const float* h0    = (const float*)d_in[7];
    const float* refEI = (const float*)d_in[8];
    const float* mwrec = (const float*)d_in[9];
    float* out = (float*)d_out;

    cudaFuncSetAttribute(k_rnn, cudaFuncAttributeMaxDynamicSharedMemorySize, SMEM_BYTES);
    k_build_M<<<(H_ * H_ + 255) / 256, 256>>>(wrec, mwrec, refEI, g);
    k_init_rs<<<(B_ * H_ + 255) / 256, 256>>>(h0, bvec);
    k_out0<<<1, 256>>>(h0, bvec, wout, out);
    k_rnn<<<GRID_, NTHR, SMEM_BYTES>>>(x, noise, wi, wout, bvec, h0, out);
}

// round 15
// speedup vs baseline: 2.2399x; 1.0627x over previous
#include <cuda_runtime.h>
#include <cuda_bf16.h>
#include <math.h>

#define B_ 256
#define T_ 500
#define I_ 8
#define H_ 1024
#define O_ 8
#define ALPHA_ 0.2f
#define NSTD_ 0.05f

#define GRID_ 128
#define NTHR 512
#define PLANE 32768                 // one 128x128 bf16 plane (256B rows)

#define SM_B_OFF 0                  // 2 static M planes (64 KB, resident all steps)
#define SM_A_OFF 65536              // 2 r planes (64 KB, restaged per step; reused for D/s_po)
#define SM_WIO_OFF 133120           // wi cache (64 f) + wout cache (64 f)
#define SMEM_BYTES 133696

// swizzled byte offset in a [row][256B] plane: XOR bits 5-7 with row&7
#define SWZ(row, cb) ((unsigned)((row) * 256 + ((cb) ^ (((row) & 7) << 5))))

__device__ float g_M[H_ * H_];                       // M[k][j] = relu(g[k])*effW[j][k]
__device__ __align__(16) unsigned short g_rs[2 * 2 * B_ * H_];  // r planes [buf][p][b][h]
__device__ float g_part[8 * H_ * B_];                // partials [ks][j][b]
__device__ float g_outp[2 * 128 * 2048];             // out partials [buf][cta][b*8+o]
__device__ unsigned g_bar;
__device__ unsigned g_flag1[8];                      // per-j-tile partial-ready counters

__device__ __forceinline__ float softplus_f(float v) {
    return fmaxf(v, 0.0f) + log1pf(expf(-fabsf(v)));
}
__device__ __forceinline__ void cp16(unsigned dst, const void* src) {
    asm volatile("cp.async.cg.shared.global [%0], [%1], 16;" :: "r"(dst), "l"(src));
}
__device__ __forceinline__ void split2(float v, unsigned short* s) {
    __nv_bfloat16 b0 = __float2bfloat16_rn(v);
    __nv_bfloat16 b1 = __float2bfloat16_rn(v - __bfloat162float(b0));
    s[0] = __bfloat16_as_ushort(b0);
    s[1] = __bfloat16_as_ushort(b1);
}
__device__ __forceinline__ void mma16816(float* d, const unsigned* a, const unsigned* b) {
    asm volatile("mma.sync.aligned.m16n8k16.row.col.f32.bf16.bf16.f32 "
        "{%0,%1,%2,%3}, {%4,%5,%6,%7}, {%8,%9}, {%0,%1,%2,%3};"
        : "+f"(d[0]), "+f"(d[1]), "+f"(d[2]), "+f"(d[3])
        : "r"(a[0]), "r"(a[1]), "r"(a[2]), "r"(a[3]), "r"(b[0]), "r"(b[1]));
}

// ---- setup 0: build M + reset sync state ----
__global__ void k_build_M(const float* __restrict__ wrec, const float* __restrict__ mwrec,
                          const float* __restrict__ refEI, const float* __restrict__ g) {
    int n = blockIdx.x * blockDim.x + threadIdx.x;   // n = j*H + k
    if (n == 0) { g_bar = 0u;
#pragma unroll
        for (int i = 0; i < 8; ++i) g_flag1[i] = 0u;
    }
    if (n >= H_ * H_) return;
    int j = n >> 10, k = n & (H_ - 1);
    float ei = refEI[k];                              // exactly +/-1
    float e = fmaxf(wrec[n] * ei, 0.0f) * ei * mwrec[n];
    g_M[k * H_ + j] = fmaxf(g[k], 0.0f) * e;
}
// ---- setup 1: r(0) planes into buffer 0 ----
__global__ void k_init_rs(const float* __restrict__ h0, const float* __restrict__ bvec) {
    int n = blockIdx.x * blockDim.x + threadIdx.x;
    if (n >= B_ * H_) return;
    int hh = n & (H_ - 1);
    unsigned short s[2];
    split2(softplus_f(h0[hh] + bvec[hh]), s);
#pragma unroll
    for (int p = 0; p < 2; ++p) g_rs[(size_t)p * (B_ * H_) + n] = s[p];
}
// ---- setup 2: out0 + fill out[:,0,:] ----
__global__ void k_out0(const float* __restrict__ h0, const float* __restrict__ bvec,
                       const float* __restrict__ wout, float* __restrict__ out) {
    __shared__ float ws[8][O_]; __shared__ float o0[O_];
    int tid = threadIdx.x;
    float p[O_];
#pragma unroll
    for (int o = 0; o < O_; ++o) p[o] = 0.0f;
    for (int hh = tid; hh < H_; hh += 256) {
        float r0 = softplus_f(h0[hh] + bvec[hh]);
#pragma unroll
        for (int o = 0; o < O_; ++o) p[o] += r0 * wout[hh * O_ + o];
    }
#pragma unroll
    for (int d = 16; d > 0; d >>= 1)
#pragma unroll
        for (int o = 0; o < O_; ++o) p[o] += __shfl_xor_sync(0xffffffffu, p[o], d);
    if ((tid & 31) == 0) for (int o = 0; o < O_; ++o) ws[tid >> 5][o] = p[o];
    __syncthreads();
    if (tid < O_) { float s = 0; for (int w = 0; w < 8; ++w) s += ws[w][tid]; o0[tid] = s; }
    __syncthreads();
    for (int rep = 0; rep < 8; ++rep) {
        int P = rep * 256 + tid;
        out[(size_t)(P >> 3) * (T_ * O_) + (P & 7)] = o0[P & 7];
    }
}

// ---- persistent HMMA RNN ----
__global__ void __launch_bounds__(NTHR, 1)
k_rnn(const float* __restrict__ x, const float* __restrict__ noise,
      const float* __restrict__ wi, const float* __restrict__ wout,
      const float* __restrict__ bvec, const float* __restrict__ h0,
      float* __restrict__ out)
{
    extern __shared__ char smc[];
    unsigned su;
    asm("{ .reg .u64 t; cvta.to.shared.u64 t, %1; cvt.u32.u64 %0, t; }" : "=r"(su) : "l"(smc));
    float* wi_s   = (float*)(smc + SM_WIO_OFF);        // [jl][i]
    float* wout_s = wi_s + 64;                         // [jl][o]

    const int tid = threadIdx.x, lane = tid & 31, w = tid >> 5, cta = blockIdx.x;
    const int bh = cta & 1, jt = (cta >> 1) & 7, ks = cta >> 4;
    const int j0 = jt * 128, k0 = ks * 128;
    const int m0 = (w & 3) * 32, n0 = (w >> 2) * 32;   // warp tile in CTA GEMM
    const int g = lane >> 2, tg = lane & 3;            // mma fragment coords
    // reducer role: b = tid&255, 4 j starting at cta*8 + (tid>>8)*4
    const int rb = tid & 255, rjj = tid >> 8, rjb = cta * 8 + rjj * 4;
    const int myjt = cta >> 4;                         // reducer's j-tile = (cta*8)/128

    // ---- static B planes: Bp[j][k] = split_p(M[k0+k][j0+j]) ----
    for (int e = tid; e < 16384; e += NTHR) {
        int jl = e >> 7, k = e & 127;
        unsigned short s[2];
        split2(__ldg(g_M + (size_t)(k0 + k) * H_ + j0 + jl), s);
#pragma unroll
        for (int p = 0; p < 2; ++p)
            *(unsigned short*)(smc + SM_B_OFF + p * PLANE + SWZ(jl, k * 2)) = s[p];
    }
    // ---- time-invariant wi/wout cache for this CTA's 8 reducer j's ----
    if (tid < 64) {
        int jl = tid >> 3, i = tid & 7;
        wi_s[tid] = wi[i * H_ + cta * 8 + jl];
    } else if (tid < 128) {
        int q = tid - 64, jl = q >> 3, o = q & 7;
        wout_s[q] = wout[(size_t)(cta * 8 + jl) * O_ + o];
    }
    float h[4], bT[4];
#pragma unroll
    for (int jj = 0; jj < 4; ++jj) { h[jj] = h0[rjb + jj]; bT[jj] = bvec[rjb + jj]; }
    __syncthreads();

    unsigned epoch = 0;
    for (int t = 0; t < T_ - 1; ++t) {
        // ---- stage A planes from g_rs buf[t&1] ----
        const size_t rs_base = (size_t)(t & 1) * (2 * B_ * H_);
#pragma unroll
        for (int rep = 0; rep < 8; ++rep) {
            int idx = rep * NTHR + tid;
            int p = idx >> 11, rem = idx & 2047, row = rem >> 4, ch = rem & 15;
            cp16(su + SM_A_OFF + p * PLANE + SWZ(row, ch * 16),
                 (const char*)g_rs + (rs_base + (size_t)p * (B_ * H_)
                     + (size_t)(bh * 128 + row) * H_ + k0) * 2 + ch * 16);
        }
        asm volatile("cp.async.commit_group;" ::: "memory");

        // ---- overlapped: out[:, t, :] from prev step's partials (buf (t-1)&1) ----
        if (t >= 1) {
            int pp = tid >> 5;
            int P = cta * 16 + pp;
            const float* src = g_outp + (size_t)((t - 1) & 1) * (128 * 2048) + P;
            float v = __ldcg(src + (size_t)lane * 2048)
                    + __ldcg(src + (size_t)(lane + 32) * 2048)
                    + __ldcg(src + (size_t)(lane + 64) * 2048)
                    + __ldcg(src + (size_t)(lane + 96) * 2048);
#pragma unroll
            for (int d = 16; d > 0; d >>= 1) v += __shfl_xor_sync(0xffffffffu, v, d);
            if (lane == 0)
                out[(size_t)(P >> 3) * (T_ * O_) + (size_t)t * O_ + (P & 7)] = v;
        }
        asm volatile("cp.async.wait_group 0;" ::: "memory");
        __syncthreads();

        // ---- GEMM: 4 split-products (2-split x 2-split), fp32 accum ----
        float d[2][4][4];
#pragma unroll
        for (int mi = 0; mi < 2; ++mi)
#pragma unroll
            for (int ni = 0; ni < 4; ++ni)
#pragma unroll
                for (int q = 0; q < 4; ++q) d[mi][ni][q] = 0.0f;

#pragma unroll 1
        for (int kk = 0; kk < 8; ++kk) {
            const int cb0 = kk * 32 + tg * 4, cb1 = cb0 + 16;
            unsigned af[2][2][4], bf[4][2][2];
#pragma unroll
            for (int mi = 0; mi < 2; ++mi) {
                int r0 = m0 + mi * 16 + g, r1 = r0 + 8;
#pragma unroll
                for (int p = 0; p < 2; ++p) {
                    const char* base = smc + SM_A_OFF + p * PLANE;
                    af[mi][p][0] = *(const unsigned*)(base + SWZ(r0, cb0));
                    af[mi][p][1] = *(const unsigned*)(base + SWZ(r1, cb0));
                    af[mi][p][2] = *(const unsigned*)(base + SWZ(r0, cb1));
                    af[mi][p][3] = *(const unsigned*)(base + SWZ(r1, cb1));
                }
            }
#pragma unroll
            for (int ni = 0; ni < 4; ++ni) {
                int rw = n0 + ni * 8 + g;
#pragma unroll
                for (int p = 0; p < 2; ++p) {
                    const char* base = smc + SM_B_OFF + p * PLANE;
                    bf[ni][p][0] = *(const unsigned*)(base + SWZ(rw, cb0));
                    bf[ni][p][1] = *(const unsigned*)(base + SWZ(rw, cb1));
                }
            }
            const int PA[4] = {0, 0, 1, 1}, PB[4] = {0, 1, 0, 1};
#pragma unroll
            for (int pr = 0; pr < 4; ++pr)
#pragma unroll
                for (int mi = 0; mi < 2; ++mi)
#pragma unroll
                    for (int ni = 0; ni < 4; ++ni)
                        mma16816(d[mi][ni], af[mi][PA[pr]], bf[ni][PB[pr]]);
        }
        __syncthreads();                 // A reads done; reuse region for D staging

        // ---- D -> smem transposed [j][b] (stride 132 = conflict-free) ----
        float* sm_out = (float*)(smc + SM_A_OFF);
#pragma unroll
        for (int mi = 0; mi < 2; ++mi)
#pragma unroll
            for (int ni = 0; ni < 4; ++ni) {
                int jl = n0 + ni * 8 + tg * 2, bl = m0 + mi * 16 + g;
                sm_out[jl * 132 + bl]           = d[mi][ni][0];
                sm_out[(jl + 1) * 132 + bl]     = d[mi][ni][1];
                sm_out[jl * 132 + bl + 8]       = d[mi][ni][2];
                sm_out[(jl + 1) * 132 + bl + 8] = d[mi][ni][3];
            }
        __syncthreads();
#pragma unroll
        for (int rep = 0; rep < 8; ++rep) {
            int q = rep * NTHR + tid, jl = q >> 5, f4 = (q & 31) * 4;
            float4 v = *(const float4*)(sm_out + jl * 132 + f4);
            *(float4*)(g_part + (size_t)ks * (H_ * B_)
                       + (size_t)(j0 + jl) * B_ + bh * 128 + f4) = v;
        }
        // ---- signal: this CTA's partials for j-tile jt are ready ----
        __syncthreads();
        if (tid == 0) { __threadfence(); atomicAdd(&g_flag1[jt], 1u); }

        // ---- prefetch reducer inputs (DRAM latency hidden under flag wait) ----
        float4 xv0 = __ldg((const float4*)(x + (size_t)rb * (T_ * I_) + (size_t)t * I_));
        float4 xv1 = __ldg((const float4*)(x + (size_t)rb * (T_ * I_) + (size_t)t * I_ + 4));
        float4 nz = __ldg((const float4*)(noise + (size_t)rb * (T_ * H_) + (size_t)t * H_ + rjb));

        // ---- wait for the 16 producers of MY j-tile ----
        if (tid == 0) {
            const unsigned target = 16u * (unsigned)(t + 1);
            while (*(volatile unsigned*)&g_flag1[myjt] < target) { }
        }
        __syncthreads();

        // ---- reducer: b = rb, j in [rjb, rjb+4) ----
        float acc[4] = {0.f, 0.f, 0.f, 0.f};
#pragma unroll
        for (int jj = 0; jj < 4; ++jj)
#pragma unroll
            for (int kr = 0; kr < 8; ++kr)
                acc[jj] += __ldcg(g_part + (size_t)kr * (H_ * B_)
                                  + (size_t)(rjb + jj) * B_ + rb);
        const float* nzp = &nz.x;
        float rn[4];
#pragma unroll
        for (int jj = 0; jj < 4; ++jj) {
            const float* wv = wi_s + (rjj * 4 + jj) * 8;
            float inp = xv0.x * wv[0] + xv0.y * wv[1] + xv0.z * wv[2] + xv0.w * wv[3]
                      + xv1.x * wv[4] + xv1.y * wv[5] + xv1.z * wv[6] + xv1.w * wv[7];
            float hv = h[jj];
            hv = hv + NSTD_ * nzp[jj] + ALPHA_ * (-hv + acc[jj] + inp);
            h[jj] = hv;
            rn[jj] = softplus_f(hv + bT[jj]);
        }
        {
            unsigned short s0[2], s1[2], s2[2], s3[2];
            split2(rn[0], s0); split2(rn[1], s1); split2(rn[2], s2); split2(rn[3], s3);
            const size_t wr_base = (size_t)((t + 1) & 1) * (2 * B_ * H_);
#pragma unroll
            for (int p = 0; p < 2; ++p) {
                ushort4 v4 = make_ushort4(s0[p], s1[p], s2[p], s3[p]);
                *(ushort4*)(g_rs + wr_base + (size_t)p * (B_ * H_) + (size_t)rb * H_ + rjb) = v4;
            }
        }
        float p[O_];
#pragma unroll
        for (int o = 0; o < O_; ++o) p[o] = 0.0f;
#pragma unroll
        for (int jj = 0; jj < 4; ++jj) {
            const float* wv = wout_s + (rjj * 4 + jj) * 8;
            float rv = rn[jj];
#pragma unroll
            for (int o = 0; o < O_; ++o) p[o] += rv * wv[o];
        }
        // fold the two j-halves in smem, then ONE coalesced slice per CTA
        float* s_po = (float*)(smc + SM_A_OFF);     // 2 x 256 x 8 floats = 16 KB
        {
            float4* st = (float4*)(s_po + ((size_t)rjj * 256 + rb) * O_);
            st[0] = make_float4(p[0], p[1], p[2], p[3]);
            st[1] = make_float4(p[4], p[5], p[6], p[7]);
        }
        __syncthreads();
#pragma unroll
        for (int q = 0; q < 4; ++q) {
            int idx = tid * 4 + q;                  // b*8+o in [0,2048)
            g_outp[(size_t)(t & 1) * (128 * 2048) + (size_t)cta * 2048 + idx]
                = s_po[idx] + s_po[2048 + idx];
        }
        // ---- full barrier (one per step): protects g_rs staging + g_outp/g_part reuse ----
        epoch++; __syncthreads();
        if (tid == 0) {
            __threadfence(); atomicAdd(&g_bar, 1u);
            while (*(volatile unsigned*)&g_bar < epoch * GRID_) { }
        }
        __syncthreads();
    }

    // ---- final output: out[:, T-1, :] from buf (T-2)&1 ----
    {
        int pp = tid >> 5, P = cta * 16 + pp;
        const float* src = g_outp + (size_t)((T_ - 2) & 1) * (128 * 2048) + P;
        float v = __ldcg(src + (size_t)lane * 2048)
                + __ldcg(src + (size_t)(lane + 32) * 2048)
                + __ldcg(src + (size_t)(lane + 64) * 2048)
                + __ldcg(src + (size_t)(lane + 96) * 2048);
#pragma unroll
        for (int d = 16; d > 0; d >>= 1) v += __shfl_xor_sync(0xffffffffu, v, d);
        if (lane == 0)
            out[(size_t)(P >> 3) * (T_ * O_) + (size_t)(T_ - 1) * O_ + (P & 7)] = v;
    }
}

extern "C" void kernel_launch(void* const* d_in, const int* in_sizes, int n_in,
                              void* d_out, int out_size) {
    const float* x     = (const float*)d_in[0];
    const float* noise = (const float*)d_in[1];
    const float* wi    = (const float*)d_in[2];
    const float* wrec  = (const float*)d_in[3];
    const float* wout  = (const float*)d_in[4];
    const float* bvec  = (const float*)d_in[5];
    const float* g     = (const float*)d_in[6];
    const float* h0    = (const float*)d_in[7];
    const float* refEI = (const float*)d_in[8];
    const float* mwrec = (const float*)d_in[9];
    float* out = (float*)d_out;

    cudaFuncSetAttribute(k_rnn, cudaFuncAttributeMaxDynamicSharedMemorySize, SMEM_BYTES);
    k_build_M<<<(H_ * H_ + 255) / 256, 256>>>(wrec, mwrec, refEI, g);
    k_init_rs<<<(B_ * H_ + 255) / 256, 256>>>(h0, bvec);
    k_out0<<<1, 256>>>(h0, bvec, wout, out);
    k_rnn<<<GRID_, NTHR, SMEM_BYTES>>>(x, noise, wi, wout, bvec, h0, out);
}